// round 15
// baseline (speedup 1.0000x reference)
#include <cuda_runtime.h>
#include <math.h>

#define Bn 16
#define Cn 256
#define Ln 64
#define Nn 8192
#define Hn 8
#define HC 32          // C / H
#define Mn 12
#define SQRT32 5.656854249492381f
#define RS_BN 0.9999950000374997f   // 1/sqrt(1 + 1e-5)
#define PI_F 3.14159265358979323846f

// ---------------- scratch (device globals; no allocation) ----------------
__device__ float g_xncol[Bn * Cn];          // xn_pre per (b,c) (const along n)

// packed f32x2 helpers (Blackwell): IEEE-exact pairwise fp32 ops
__device__ __forceinline__ void fma2(unsigned long long& d,
                                     unsigned long long a,
                                     unsigned long long b) {
    asm("fma.rn.f32x2 %0, %1, %2, %0;" : "+l"(d) : "l"(a), "l"(b));
}
__device__ __forceinline__ unsigned long long add2(unsigned long long a,
                                                   unsigned long long b) {
    unsigned long long r;
    asm("add.rn.f32x2 %0, %1, %2;" : "=l"(r) : "l"(a), "l"(b));
    return r;
}
__device__ __forceinline__ unsigned long long dup2(float w) {
    unsigned long long r;
    asm("mov.b64 %0, {%1, %1};" : "=l"(r) : "f"(w));
    return r;
}
__device__ __forceinline__ float2 unpk(unsigned long long a) {
    float lo, hi;
    asm("mov.b64 {%0, %1}, %2;" : "=f"(lo), "=f"(hi) : "l"(a));
    return make_float2(lo, hi);
}

// dynamic smem layout (bytes)
#define OFF_XS   0                       // ulonglong2[256*16]  xt[b] as [j=256][s=64]
#define OFF_QS   65536                   // float[64*33]  Q[s][c]
#define OFF_KS   (OFF_QS + 8448)
#define OFF_VS   (OFF_KS + 8448)
#define OFF_ES   (OFF_VS + 8448)         // float[32*65]  encoder-out [c][l]
#define OFF_WS   (OFF_ES + 8320)         // float[32*24]
#define OFF_MASK (OFF_WS + 3072)         // float[256]
#define OFF_QD   (OFF_MASK + 1024)       // float[32]
#define OFF_PS   (OFF_QD + 128)          // float[64]
#define OFF_PART (OFF_PS + 256)          // ulonglong2[96*16]  kh=1 GEMM partials
#define SMEM_TOTAL (OFF_PART + 24576)    // 128256 B

// ---------------- kernel 1: QKV GEMM + enc-attn + fourier + dec-attn ----------------
// grid (H, B), block 512.
// GEMM: kh = t>>8 (k-half), ch = (t>>3)&31 (channel), cg = t&7 (8 L-cols each).
// kh=1 writes partials to smem scratch (stride 16/channel); kh=0 combines + bias.
// Attention: warp w covers l = w*4 + (lane>>3); g = lane&7.
__global__ void __launch_bounds__(512) k_fused(const float* __restrict__ xt,
                                               const float* __restrict__ enc_w,
                                               const float* __restrict__ enc_b,
                                               const float* __restrict__ weights,
                                               const float* __restrict__ mask_token,
                                               const float* __restrict__ dec_w,
                                               const float* __restrict__ dec_b)
{
    extern __shared__ char smem[];
    ulonglong2* xs4   = (ulonglong2*)(smem + OFF_XS);
    float* qs         = (float*)(smem + OFF_QS);
    float* ks         = (float*)(smem + OFF_KS);
    float* vs         = (float*)(smem + OFF_VS);
    float* es         = (float*)(smem + OFF_ES);
    float* ws         = (float*)(smem + OFF_WS);
    float* mask_s     = (float*)(smem + OFF_MASK);
    float* q_s        = (float*)(smem + OFF_QD);
    float* p_s        = (float*)(smem + OFF_PS);
    ulonglong2* part  = (ulonglong2*)(smem + OFF_PART);   // [(m*32+ch)*16 + cg*2 + {0,1}]

    const int h = blockIdx.x, b = blockIdx.y;
    const int t = threadIdx.x;
    const int lane = t & 31;

    // ---- stage xt[b] (64 KB), mask, fourier weights ----
    {
        const ulonglong2* xb4 = (const ulonglong2*)(xt + (size_t)b * Cn * Ln);
        #pragma unroll
        for (int i = 0; i < 8; i++) xs4[t + i * 512] = xb4[t + i * 512];
    }
    if (t < Cn) mask_s[t] = mask_token[t];
    for (int i = t; i < HC * 24; i += 512) {
        int cc = i / 24, m = i - cc * 24;
        ws[i] = weights[(h * HC + cc) * 24 + m];
    }
    __syncthreads();

    // ---- QKV GEMM: 96 rows x 64 cols, k split in halves across the block ----
    {
        const int kh = t >> 8;           // k-half: 0 or 1
        const int u  = t & 255;
        const int ch = u >> 3;           // channel within head: 0..31
        const int cg = u & 7;            // col group: cols cg*8..cg*8+7

        const float4* wq = (const float4*)(enc_w + (size_t)(h * HC + ch) * Cn) + kh * 32;
        const float4* wk = wq + (Cn * Cn / 4);
        const float4* wv = wk + (Cn * Cn / 4);
        const int xbase0 = kh * 128 * 16 + cg * 2;

        unsigned long long aq0=0,aq1=0,aq2=0,aq3=0;
        unsigned long long ak0=0,ak1=0,ak2=0,ak3=0;
        unsigned long long av0=0,av1=0,av2=0,av3=0;

        #pragma unroll 8
        for (int j4 = 0; j4 < 32; j4++) {
            const float4 q4 = wq[j4], k4 = wk[j4], v4 = wv[j4];
            #pragma unroll
            for (int jj = 0; jj < 4; jj++) {
                const int xb2 = xbase0 + (j4 * 4 + jj) * 16;
                const ulonglong2 xa = xs4[xb2];
                const ulonglong2 xb = xs4[xb2 + 1];
                const float wqv = (jj==0)?q4.x:(jj==1)?q4.y:(jj==2)?q4.z:q4.w;
                const float wkv = (jj==0)?k4.x:(jj==1)?k4.y:(jj==2)?k4.z:k4.w;
                const float wvv = (jj==0)?v4.x:(jj==1)?v4.y:(jj==2)?v4.z:v4.w;
                unsigned long long d;
                d = dup2(wqv); fma2(aq0,d,xa.x); fma2(aq1,d,xa.y); fma2(aq2,d,xb.x); fma2(aq3,d,xb.y);
                d = dup2(wkv); fma2(ak0,d,xa.x); fma2(ak1,d,xa.y); fma2(ak2,d,xb.x); fma2(ak3,d,xb.y);
                d = dup2(wvv); fma2(av0,d,xa.x); fma2(av1,d,xa.y); fma2(av2,d,xb.x); fma2(av3,d,xb.y);
            }
        }

        if (kh == 1) {
            ulonglong2* pq = part + (0 * 32 + ch) * 16 + cg * 2;
            ulonglong2* pk = part + (1 * 32 + ch) * 16 + cg * 2;
            ulonglong2* pv = part + (2 * 32 + ch) * 16 + cg * 2;
            pq[0] = make_ulonglong2(aq0, aq1); pq[1] = make_ulonglong2(aq2, aq3);
            pk[0] = make_ulonglong2(ak0, ak1); pk[1] = make_ulonglong2(ak2, ak3);
            pv[0] = make_ulonglong2(av0, av1); pv[1] = make_ulonglong2(av2, av3);
        }
        __syncthreads();
        if (kh == 0) {
            const ulonglong2* pq = part + (0 * 32 + ch) * 16 + cg * 2;
            const ulonglong2* pk = part + (1 * 32 + ch) * 16 + cg * 2;
            const ulonglong2* pv = part + (2 * 32 + ch) * 16 + cg * 2;
            const unsigned long long bq2 = dup2(enc_b[h * HC + ch]);
            const unsigned long long bk2 = dup2(enc_b[Cn + h * HC + ch]);
            const unsigned long long bv2 = dup2(enc_b[2 * Cn + h * HC + ch]);
            ulonglong2 r0, r1;
            const int s0 = cg * 8;

            r0 = pq[0]; r1 = pq[1];
            aq0 = add2(add2(aq0, r0.x), bq2); aq1 = add2(add2(aq1, r0.y), bq2);
            aq2 = add2(add2(aq2, r1.x), bq2); aq3 = add2(add2(aq3, r1.y), bq2);
            r0 = pk[0]; r1 = pk[1];
            ak0 = add2(add2(ak0, r0.x), bk2); ak1 = add2(add2(ak1, r0.y), bk2);
            ak2 = add2(add2(ak2, r1.x), bk2); ak3 = add2(add2(ak3, r1.y), bk2);
            r0 = pv[0]; r1 = pv[1];
            av0 = add2(add2(av0, r0.x), bv2); av1 = add2(add2(av1, r0.y), bv2);
            av2 = add2(add2(av2, r1.x), bv2); av3 = add2(add2(av3, r1.y), bv2);

            float2 f;
            f = unpk(aq0); qs[(s0+0)*33+ch] = f.x; qs[(s0+1)*33+ch] = f.y;
            f = unpk(aq1); qs[(s0+2)*33+ch] = f.x; qs[(s0+3)*33+ch] = f.y;
            f = unpk(aq2); qs[(s0+4)*33+ch] = f.x; qs[(s0+5)*33+ch] = f.y;
            f = unpk(aq3); qs[(s0+6)*33+ch] = f.x; qs[(s0+7)*33+ch] = f.y;
            f = unpk(ak0); ks[(s0+0)*33+ch] = f.x; ks[(s0+1)*33+ch] = f.y;
            f = unpk(ak1); ks[(s0+2)*33+ch] = f.x; ks[(s0+3)*33+ch] = f.y;
            f = unpk(ak2); ks[(s0+4)*33+ch] = f.x; ks[(s0+5)*33+ch] = f.y;
            f = unpk(ak3); ks[(s0+6)*33+ch] = f.x; ks[(s0+7)*33+ch] = f.y;
            f = unpk(av0); vs[(s0+0)*33+ch] = f.x; vs[(s0+1)*33+ch] = f.y;
            f = unpk(av1); vs[(s0+2)*33+ch] = f.x; vs[(s0+3)*33+ch] = f.y;
            f = unpk(av2); vs[(s0+4)*33+ch] = f.x; vs[(s0+5)*33+ch] = f.y;
            f = unpk(av3); vs[(s0+6)*33+ch] = f.x; vs[(s0+7)*33+ch] = f.y;
        }
    }
    __syncthreads();

    // ---- encoder attention ----
    const int l = (t >> 5) * 4 + (lane >> 3);
    const int g = lane & 7;

    float q[HC];
    #pragma unroll
    for (int cc = 0; cc < HC; cc++) q[cc] = qs[l * 33 + cc];

    float dloc[8];
    float mx = -1e30f;
    #pragma unroll
    for (int i = 0; i < 8; i++) {
        const int s = g + i * 8;
        float d = 0.f;
        #pragma unroll
        for (int cc = 0; cc < HC; cc++) d = fmaf(q[cc], ks[s * 33 + cc], d);
        d *= SQRT32;
        dloc[i] = d;
        mx = fmaxf(mx, d);
    }
    mx = fmaxf(mx, __shfl_xor_sync(0xffffffffu, mx, 1));
    mx = fmaxf(mx, __shfl_xor_sync(0xffffffffu, mx, 2));
    mx = fmaxf(mx, __shfl_xor_sync(0xffffffffu, mx, 4));

    float sum = 0.f;
    #pragma unroll
    for (int i = 0; i < 8; i++) {
        const float e = __expf(dloc[i] - mx);
        dloc[i] = e;
        sum += e;
    }
    sum += __shfl_xor_sync(0xffffffffu, sum, 1);
    sum += __shfl_xor_sync(0xffffffffu, sum, 2);
    sum += __shfl_xor_sync(0xffffffffu, sum, 4);
    const float inv = 1.f / sum;

    float acc[4];
    #pragma unroll
    for (int j = 0; j < 4; j++) acc[j] = 0.f;
    #pragma unroll 16
    for (int s = 0; s < 64; s++) {
        const int src = (lane & 24) | (s & 7);
        const float p = __shfl_sync(0xffffffffu, dloc[s >> 3], src);
        #pragma unroll
        for (int j = 0; j < 4; j++) acc[j] = fmaf(p, vs[s * 33 + g * 4 + j], acc[j]);
    }

    // ---- fourier + residual (xt residual from the staged smem copy) ----
    const float* xs_f = (const float*)xs4;
    #pragma unroll
    for (int j = 0; j < 4; j++) {
        const int cc = g * 4 + j;
        const float a = acc[j] * inv;
        const float phi = a * (PI_F / (float)Mn);
        float s1, c1;
        __sincosf(phi, &s1, &c1);
        const float* w = ws + cc * 24;
        float fv = w[Mn];
        float sm = s1, cm = c1;
        #pragma unroll
        for (int m = 1; m < Mn; m++) {
            fv = fmaf(w[m], sm, fv);
            fv = fmaf(w[Mn + m], cm, fv);
            float sn = sm * c1 + cm * s1;
            cm = cm * c1 - sm * s1;
            sm = sn;
        }
        es[cc * 65 + l] = fv + xs_f[(h * HC + cc) * Ln + l];
    }

    // ---- decoder q: 16 threads per output row ----
    {
        const int c = t >> 4, part2 = t & 15;
        const int row = h * HC + c;
        const float4* wp = (const float4*)(dec_w + row * Cn) + part2 * 4;
        const float4* mp = (const float4*)(mask_s) + part2 * 4;
        float a4 = 0.f;
        #pragma unroll
        for (int i = 0; i < 4; i++) {
            float4 w4 = wp[i], m4 = mp[i];
            a4 = fmaf(w4.x, m4.x, a4); a4 = fmaf(w4.y, m4.y, a4);
            a4 = fmaf(w4.z, m4.z, a4); a4 = fmaf(w4.w, m4.w, a4);
        }
        a4 += __shfl_xor_sync(0xffffffffu, a4, 1);
        a4 += __shfl_xor_sync(0xffffffffu, a4, 2);
        a4 += __shfl_xor_sync(0xffffffffu, a4, 4);
        a4 += __shfl_xor_sync(0xffffffffu, a4, 8);
        if (part2 == 0) q_s[c] = a4 + dec_b[row];
    }
    __syncthreads();

    if (t < Ln) {
        float d = 0.f;
        #pragma unroll
        for (int cc = 0; cc < HC; cc++) d = fmaf(q_s[cc], es[cc * 65 + t], d);
        p_s[t] = d * SQRT32;
    }
    __syncthreads();

    if (t < 32) {
        float v0 = p_s[t], v1 = p_s[t + 32];
        float m = fmaxf(v0, v1);
        #pragma unroll
        for (int off2 = 16; off2; off2 >>= 1) m = fmaxf(m, __shfl_xor_sync(0xffffffffu, m, off2));
        float e0 = __expf(v0 - m), e1 = __expf(v1 - m);
        float s = e0 + e1;
        #pragma unroll
        for (int off2 = 16; off2; off2 >>= 1) s += __shfl_xor_sync(0xffffffffu, s, off2);
        float pin = 1.f / s;
        p_s[t]      = e0 * pin;
        p_s[t + 32] = e1 * pin;
    }
    __syncthreads();

    if (t < HC) {
        float a5 = 0.f;
        #pragma unroll
        for (int ll = 0; ll < Ln; ll++) a5 = fmaf(p_s[ll], es[t * 65 + ll], a5);
        g_xncol[b * Cn + h * HC + t] = a5 + mask_s[h * HC + t];
    }
}

// ---------------- kernel 2: broadcast (R7-proven layout) + head MLP ----------------
// Blocks 0..511: warp-per-(b,c)-row, 64 streaming float4 stores per lane.
// Blocks 512..527: per-batch fc1->fc2, then stream y.
__global__ void __launch_bounds__(256) k_bcast(float4* __restrict__ out4,
                                               const float* __restrict__ fc1_w,
                                               const float* __restrict__ fc1_g,
                                               const float* __restrict__ fc1_b,
                                               const float* __restrict__ fc2_w,
                                               const float* __restrict__ fc2_g,
                                               const float* __restrict__ fc2_b)
{
    const int t = threadIdx.x;
    if (blockIdx.x < 512) {
        const int warp = t >> 5, lane = t & 31;
        const int row = blockIdx.x * 8 + warp;          // b*Cn + c
        const float v = g_xncol[row];
        const float4 v4 = make_float4(v, v, v, v);
        float4* p = out4 + (size_t)row * 2048 + lane;
        #pragma unroll 16
        for (int i = 0; i < 64; i++) __stcs(p + i * 32, v4);
    } else {
        __shared__ float xn_s[Cn];
        __shared__ float y1_s[Cn];
        __shared__ float y2_s[3];
        const int b = blockIdx.x - 512;

        xn_s[t] = g_xncol[b * Cn + t];
        __syncthreads();

        {
            float acc = 0.f;
            const float4* wr = (const float4*)(fc1_w + t * Cn);
            const float4* xr = (const float4*)xn_s;
            #pragma unroll 8
            for (int i = 0; i < 64; i++) {
                float4 w4 = wr[i], x4 = xr[i];
                acc = fmaf(w4.x, x4.x, acc); acc = fmaf(w4.y, x4.y, acc);
                acc = fmaf(w4.z, x4.z, acc); acc = fmaf(w4.w, x4.w, acc);
            }
            float y = fc1_g[t] * acc * RS_BN + fc1_b[t];
            y1_s[t] = (y >= 0.f) ? y : 0.2f * y;
        }
        __syncthreads();

        {
            const int w = t >> 5, lane = t & 31;
            if (w < 3) {
                const float4* wr = (const float4*)(fc2_w + w * Cn) + lane * 2;
                const float4* yr = (const float4*)y1_s + lane * 2;
                float acc = 0.f;
                #pragma unroll
                for (int i = 0; i < 2; i++) {
                    float4 w4 = wr[i], y4 = yr[i];
                    acc = fmaf(w4.x, y4.x, acc); acc = fmaf(w4.y, y4.y, acc);
                    acc = fmaf(w4.z, y4.z, acc); acc = fmaf(w4.w, y4.w, acc);
                }
                #pragma unroll
                for (int off = 16; off; off >>= 1) acc += __shfl_xor_sync(0xffffffffu, acc, off);
                if (lane == 0) {
                    float y = fc2_g[w] * acc * RS_BN + fc2_b[w];
                    y2_s[w] = (y >= 0.f) ? y : 0.2f * y;
                }
            }
        }
        __syncthreads();

        const float y0 = y2_s[0], y1 = y2_s[1], y2v = y2_s[2];
        float4 var[3];
        var[0] = make_float4(y0, y1, y2v, y0);
        var[1] = make_float4(y1, y2v, y0, y1);
        var[2] = make_float4(y2v, y0, y1, y2v);
        float4* p = out4 + (size_t)(Bn * Cn * Nn) / 4 + (size_t)b * 6144;
        for (int i = t; i < 6144; i += 256) __stcs(p + i, var[i % 3]);
    }
}

// ---------------- launch ----------------
extern "C" void kernel_launch(void* const* d_in, const int* in_sizes, int n_in,
                              void* d_out, int out_size)
{
    const float* xt        = (const float*)d_in[0];
    /* xn = d_in[1] never read: fully-masked path */
    const float* weights   = (const float*)d_in[2];
    const float* mask_tok  = (const float*)d_in[3];
    const float* enc_w     = (const float*)d_in[4];
    const float* enc_b     = (const float*)d_in[5];
    const float* dec_w     = (const float*)d_in[6];
    const float* dec_b     = (const float*)d_in[7];
    const float* fc1_w     = (const float*)d_in[8];
    const float* fc1_g     = (const float*)d_in[9];
    const float* fc1_b     = (const float*)d_in[10];
    const float* fc2_w     = (const float*)d_in[11];
    const float* fc2_g     = (const float*)d_in[12];
    const float* fc2_b     = (const float*)d_in[13];
    float* out = (float*)d_out;

    // idempotent; enqueues nothing (capture-safe)
    cudaFuncSetAttribute(k_fused, cudaFuncAttributeMaxDynamicSharedMemorySize, SMEM_TOTAL);

    k_fused<<<dim3(Hn, Bn), 512, SMEM_TOTAL>>>(xt, enc_w, enc_b, weights,
                                               mask_tok, dec_w, dec_b);
    k_bcast<<<528, 256>>>((float4*)out, fc1_w, fc1_g, fc1_b, fc2_w, fc2_g, fc2_b);
}